// round 11
// baseline (speedup 1.0000x reference)
#include <cuda_runtime.h>
#include <cuda_bf16.h>
#include <cstdint>

// Problem constants
#define Nn 8
#define Cc 64
#define Hh 96
#define Ww 96
#define COo 64
#define KK9 9
#define HW 9216           // 96*96
#define NPIX 73728        // 8*9216

// ---------------- scratch (device globals; no allocation allowed) ----------------
// x NHWC, tf32 bits, channels PERMUTED within 8-groups: pos = (c&~7) | ((c&3)<<1) | ((c>>2)&1)
__device__ __align__(16) uint32_t g_xtf[Nn * Hh * Ww * Cc];
// fragment-major weights, per-k-step uint4: [t][cog][kk][lane][nt][j]
__device__ __align__(16) uint32_t g_wtf[KK9 * 4 * 8 * 32 * 4];    // main conv (36864)
__device__ __align__(16) uint32_t g_wofff[KK9 * 2 * 8 * 32 * 4];  // off conv  (18432)

static __device__ __forceinline__ uint32_t f2tf32(float v) {
    uint32_t r;
    asm("cvt.rna.tf32.f32 %0, %1;" : "=r"(r) : "f"(v));
    return r;
}
static __device__ __forceinline__ uint32_t smem_u32(const void* p) {
    uint32_t a;
    asm("{ .reg .u64 t; cvta.to.shared.u64 t, %1; cvt.u32.u64 %0, t; }" : "=r"(a) : "l"(p));
    return a;
}
static __device__ __forceinline__ void mma_tf32(float* d, const uint32_t* a, const uint32_t* b) {
    asm volatile("mma.sync.aligned.m16n8k8.row.col.f32.tf32.tf32.f32 "
                 "{%0,%1,%2,%3}, {%4,%5,%6,%7}, {%8,%9}, {%0,%1,%2,%3};"
                 : "+f"(d[0]), "+f"(d[1]), "+f"(d[2]), "+f"(d[3])
                 : "r"(a[0]), "r"(a[1]), "r"(a[2]), "r"(a[3]), "r"(b[0]), "r"(b[1]));
}
#define CP_ASYNC16(dst, src, sz) \
    asm volatile("cp.async.cg.shared.global [%0], [%1], 16, %2;" :: "r"(dst), "l"(src), "r"(sz) : "memory")
#define CP_COMMIT() asm volatile("cp.async.commit_group;" ::: "memory")
#define CP_WAIT(n)  asm volatile("cp.async.wait_group %0;" :: "n"(n) : "memory")

// ---------------- kernel 0: x transpose (2 c-tiles/block) + weight prep, one launch ----------------
#define TP_BLOCKS 2304        // 3 wtiles * 768 (n*y)
__global__ void k_prep(const float* __restrict__ x,
                       const float* __restrict__ weight,
                       const float* __restrict__ w_off) {
    int b = blockIdx.x;
    int tid = threadIdx.x;
    if (b < TP_BLOCKS) {
        __shared__ float tile[2][32][33];
        int xb = (b % 3) * 32;
        int z = b / 3;
        int n = z / Hh;
        int y = z % Hh;
        int tx = tid & 31, ty = tid >> 5;
#pragma unroll
        for (int cb2 = 0; cb2 < 2; cb2++)
#pragma unroll
            for (int k = 0; k < 4; k++) {
                int c = cb2 * 32 + ty + k * 8;
                tile[cb2][ty + k * 8][tx] = x[((n * Cc + c) * Hh + y) * Ww + xb + tx];
            }
        __syncthreads();
#pragma unroll
        for (int cb2 = 0; cb2 < 2; cb2++) {
            int c = cb2 * 32 + tx;
            int s = (c & 56) | ((c & 3) << 1) | ((c >> 2) & 1);   // permuted position
#pragma unroll
            for (int k = 0; k < 4; k++) {
                int xo = xb + ty + k * 8;
                g_xtf[((n * Hh + y) * Ww + xo) * Cc + s] = f2tf32(tile[cb2][tx][ty + k * 8]);
            }
        }
    } else {
        int gidx = (b - TP_BLOCKS) * 256 + tid;
        if (gidx < KK9 * 4096) {
            int idx = gidx;
            int j = idx & 1;
            int nt = (idx >> 1) & 1;
            int lane = (idx >> 2) & 31;
            int kk = (idx >> 7) & 7;
            int cog = (idx >> 10) & 3;
            int t = idx >> 12;
            int co = cog * 16 + nt * 8 + (lane >> 2);
            int c = kk * 8 + (lane & 3) + 4 * j;
            g_wtf[idx] = f2tf32(weight[(co * Cc + c) * KK9 + t]);
        } else if (gidx < KK9 * 4096 + KK9 * 2048) {
            int idx = gidx - KK9 * 4096;
            int j = idx & 1;
            int nt = (idx >> 1) & 1;
            int lane = (idx >> 2) & 31;
            int kk = (idx >> 7) & 7;
            int cog = (idx >> 10) & 1;
            int t = idx >> 11;
            int ch = cog * 16 + nt * 8 + (lane >> 2);
            int c = kk * 8 + (lane & 3) + 4 * j;
            g_wofff[idx] = (ch < 27) ? f2tf32(w_off[(ch * Cc + c) * KK9 + t]) : 0u;
        }
    }
}

// ---------------- fused kernel: offconv (TC) -> metadata -> deform (TC) ----------------
#define A_STRIDE 72                            // 72 ≡ 8 (mod 32): conflict-free LDS.64 frags
#define O_STRIDE 132
#define BUFW (128 * A_STRIDE)                  // 9216 words per val buffer
#define SM_ENTW (2 * BUFW * 4)                 // 73728
#define SM_ENTB (SM_ENTW + 1152 * 16)          // 92160  (obase overlays here)
#define SM_ENTD (SM_ENTB + 1152 * 4)           // 96768
#define FUSED_SMEM (SM_ENTD + 1152 * 4)        // 101376

__global__ void __launch_bounds__(512, 2) k_fused(const float* __restrict__ b_off,
                                                  const float* __restrict__ bias,
                                                  float* __restrict__ out) {
    extern __shared__ char base[];
    uint32_t* valS = (uint32_t*)base;                // [2][128][72]
    float4*   entW = (float4*)(base + SM_ENTW);
    int*      entB = (int*)(base + SM_ENTB);
    int*      entD = (int*)(base + SM_ENTD);
    int*      obase = entB;                          // overlay (dead before entB written)
    float*    offmS = (float*)base;                  // [128][28] overlay (written after phase A)
    float*    outS = (float*)base;                   // epilogue overlay [64co][132]
    uint32_t  valS_sm = smem_u32(valS);
    const float* xtf = (const float*)g_xtf;

    int tid = threadIdx.x;
    int wid = tid >> 5;
    int lane = tid & 31;
    int pix0 = blockIdx.x * 128;
    int nb = pix0 / HW;
    int rem0 = pix0 % HW;
    int lg = lane >> 2;
    int lt = lane & 3;

    // ============ phase A: offset conv (128pix x 32ch, warp tile 16pix x 16ch) ============
    for (int e = tid; e < KK9 * 128; e += 512) {
        int t = e >> 7;
        int pl = e & 127;
        int rem = rem0 + pl;
        int yy = rem / Ww + t / 3 - 1;
        int xx = rem % Ww + t % 3 - 1;
        obase[e] = ((unsigned)yy < Hh && (unsigned)xx < Ww)
                 ? ((nb * Hh + yy) * Ww + xx) * Cc : -1;
    }
    __syncthreads();

    int wmA = (wid & 7) * 16;     // warp pixel base (phase A)
    int cogA = wid >> 3;          // ch group (16 ch)

    float accA[2][4];
#pragma unroll
    for (int nt = 0; nt < 2; nt++)
#pragma unroll
        for (int r = 0; r < 4; r++) accA[nt][r] = 0.f;

    auto fillA = [&](int tt, int b) {
        uint32_t dbase = valS_sm + b * (BUFW * 4);
#pragma unroll
        for (int j = 0; j < 4; j++) {
            int idx = tid + j * 512;
            int pl = idx >> 4;
            int c4 = (idx & 15) << 2;
            int gb = obase[tt * 128 + pl];
            const uint32_t* src = &g_xtf[(gb < 0 ? 0 : gb) + c4];
            CP_ASYNC16(dbase + (pl * A_STRIDE + c4) * 4, src, (gb < 0) ? 0 : 16);
        }
        CP_COMMIT();
    };

    fillA(0, 0);
    for (int t = 0; t < KK9; t++) {
        CP_WAIT(0);
        __syncthreads();                 // fill(t) complete everywhere; mma(t-1) done everywhere
        if (t < KK9 - 1) fillA(t + 1, (t + 1) & 1);
        const uint32_t* cur = valS + (t & 1) * BUFW;
#pragma unroll
        for (int kk = 0; kk < 8; kk++) {
            int k0 = kk * 8 + 2 * lt;
            uint2 p0 = *(const uint2*)&cur[(wmA + lg) * A_STRIDE + k0];
            uint2 p1 = *(const uint2*)&cur[(wmA + 8 + lg) * A_STRIDE + k0];
            uint32_t a[4] = {p0.x, p1.x, p0.y, p1.y};
            uint4 bv = ((const uint4*)&g_wofff[((t * 2 + cogA) * 8 + kk) * 128])[lane];
            uint32_t b0[2] = {bv.x, bv.y};
            uint32_t b1[2] = {bv.z, bv.w};
            mma_tf32(accA[0], a, b0);
            mma_tf32(accA[1], a, b1);
        }
    }
    __syncthreads();                     // all mma done before offmS overlays buf0

    // phase A epilogue -> offmS
#pragma unroll
    for (int nt = 0; nt < 2; nt++)
#pragma unroll
        for (int r = 0; r < 4; r++) {
            int pix = wmA + ((r >> 1) << 3) + lg;
            int ch = cogA * 16 + nt * 8 + 2 * lt + (r & 1);
            if (ch < 27) {
                float v = accA[nt][r] + __ldg(&b_off[ch]);
                if (ch >= 18) v = 1.f / (1.f + __expf(-v));
                offmS[pix * 28 + ch] = v;
            }
        }
    __syncthreads();

    // ============ metadata: bilinear coefficients for all 9 taps ============
    for (int e = tid; e < KK9 * 128; e += 512) {
        int t = e >> 7;
        int pl = e & 127;
        int rem = rem0 + pl;
        int y = rem / Ww;
        int x = rem % Ww;
        float dy = offmS[pl * 28 + 2 * t];
        float dx = offmS[pl * 28 + 2 * t + 1];
        float m = offmS[pl * 28 + 18 + t];
        int ky = t / 3, kx = t % 3;
        float py = (float)(y + ky - 1) + dy;
        float px = (float)(x + kx - 1) + dx;
        float fy = floorf(py), fx = floorf(px);
        float ly = py - fy, lx = px - fx;
        int iy = (int)fy, ix = (int)fx;
        float hy0 = (iy >= 0 && iy < Hh) ? (1.f - ly) : 0.f;
        float hy1 = (iy >= -1 && iy < Hh - 1) ? ly : 0.f;
        float hx0 = (ix >= 0 && ix < Ww) ? (1.f - lx) : 0.f;
        float hx1 = (ix >= -1 && ix < Ww - 1) ? lx : 0.f;
        int iyc = min(max(iy, 0), Hh - 1);
        int ixc = min(max(ix, 0), Ww - 1);
        int ddy = (iy >= 0 && iy < Hh - 1) ? Ww * Cc : 0;
        int ddx = (ix >= 0 && ix < Ww - 1) ? Cc : 0;
        entB[e] = ((nb * Hh + iyc) * Ww + ixc) * Cc;   // overwrites obase (dead)
        entD[e] = ddx | (ddy << 16);
        entW[e] = make_float4(hy0 * hx0 * m, hy0 * hx1 * m, hy1 * hx0 * m, hy1 * hx1 * m);
    }

    // ============ phase B: deform (128pix x 64co, warp tile 32pix x 16co) ============
    int wm = (wid & 3) * 32;
    int cog = wid >> 2;
    int c4 = (tid & 15) << 2;     // gather channel position (float4 granule)
    int q4 = tid >> 4;            // gather pixel phase (0..31)

    float acc[2][2][4];
#pragma unroll
    for (int mt = 0; mt < 2; mt++)
#pragma unroll
        for (int nt = 0; nt < 2; nt++)
#pragma unroll
            for (int r = 0; r < 4; r++) acc[mt][nt][r] = 0.f;
    __syncthreads();              // metadata visible; offmS/valS free

    // prologue gather: tap 0 -> buf 0 (simple form)
#pragma unroll
    for (int s = 0; s < 4; s++) {
        int pl = s * 32 + q4;
        float4 w = entW[pl];
        int gbase = entB[pl] + c4;
        int dd = entD[pl];
        int ddx = dd & 0xffff;
        int ddy = dd >> 16;
        float4 v00 = *(const float4*)&xtf[gbase];
        float4 v01 = *(const float4*)&xtf[gbase + ddx];
        float4 v10 = *(const float4*)&xtf[gbase + ddy];
        float4 v11 = *(const float4*)&xtf[gbase + ddy + ddx];
        uint4 o;
        o.x = f2tf32(w.x * v00.x + w.y * v01.x + w.z * v10.x + w.w * v11.x);
        o.y = f2tf32(w.x * v00.y + w.y * v01.y + w.z * v10.y + w.w * v11.y);
        o.z = f2tf32(w.x * v00.z + w.y * v01.z + w.z * v10.z + w.w * v11.z);
        o.w = f2tf32(w.x * v00.w + w.y * v01.w + w.z * v10.w + w.w * v11.w);
        *(uint4*)&valS[pl * A_STRIDE + c4] = o;
    }
    __syncthreads();

    // mainloop: gather(t+1) slots interleaved between mma k-step pairs
    for (int t = 0; t < KK9; t++) {
        const uint32_t* cur = valS + (t & 1) * BUFW;
        uint32_t* nxt = valS + ((t + 1) & 1) * BUFW;
        bool dog = (t < KK9 - 1);
        int tb = (t + 1) * 128;
#pragma unroll
        for (int s = 0; s < 4; s++) {
            // issue slot-s gather loads (latency covered by the 2 k-steps below)
            float4 w, v00, v01, v10, v11;
            int pl = s * 32 + q4;
            if (dog) {
                int e = tb + pl;
                w = entW[e];
                int gbase = entB[e] + c4;
                int dd = entD[e];
                int ddx = dd & 0xffff;
                int ddy = dd >> 16;
                v00 = *(const float4*)&xtf[gbase];
                v01 = *(const float4*)&xtf[gbase + ddx];
                v10 = *(const float4*)&xtf[gbase + ddy];
                v11 = *(const float4*)&xtf[gbase + ddy + ddx];
            }
#pragma unroll
            for (int kk2 = 0; kk2 < 2; kk2++) {
                int kk = s * 2 + kk2;
                int k0 = kk * 8 + 2 * lt;
                uint32_t a[2][4];
#pragma unroll
                for (int mt = 0; mt < 2; mt++) {
                    uint2 p0 = *(const uint2*)&cur[(wm + mt * 16 + lg) * A_STRIDE + k0];
                    uint2 p1 = *(const uint2*)&cur[(wm + mt * 16 + 8 + lg) * A_STRIDE + k0];
                    a[mt][0] = p0.x; a[mt][1] = p1.x; a[mt][2] = p0.y; a[mt][3] = p1.y;
                }
                uint4 bv = ((const uint4*)&g_wtf[((t * 4 + cog) * 8 + kk) * 128])[lane];
                uint32_t b0[2] = {bv.x, bv.y};
                uint32_t b1[2] = {bv.z, bv.w};
#pragma unroll
                for (int mt = 0; mt < 2; mt++) {
                    mma_tf32(acc[mt][0], a[mt], b0);
                    mma_tf32(acc[mt][1], a[mt], b1);
                }
            }
            if (dog) {
                uint4 o;
                o.x = f2tf32(w.x * v00.x + w.y * v01.x + w.z * v10.x + w.w * v11.x);
                o.y = f2tf32(w.x * v00.y + w.y * v01.y + w.z * v10.y + w.w * v11.y);
                o.z = f2tf32(w.x * v00.z + w.y * v01.z + w.z * v10.z + w.w * v11.z);
                o.w = f2tf32(w.x * v00.w + w.y * v01.w + w.z * v10.w + w.w * v11.w);
                *(uint4*)&nxt[pl * A_STRIDE + c4] = o;
            }
        }
        __syncthreads();
    }

    // epilogue: fragments -> smem [co][pix] -> coalesced NCHW stores
#pragma unroll
    for (int mt = 0; mt < 2; mt++)
#pragma unroll
        for (int nt = 0; nt < 2; nt++)
#pragma unroll
            for (int r = 0; r < 4; r++) {
                int pix = wm + mt * 16 + ((r >> 1) << 3) + lg;
                int co = cog * 16 + nt * 8 + 2 * lt + (r & 1);
                outS[co * O_STRIDE + pix] = acc[mt][nt][r];
            }
    __syncthreads();

#pragma unroll
    for (int i = 0; i < 4; i++) {
        int co = i * 16 + wid;
        int px = lane * 4;
        float4 v = *(const float4*)&outS[co * O_STRIDE + px];
        float bv = __ldg(&bias[co]);
        v.x += bv; v.y += bv; v.z += bv; v.w += bv;
        *(float4*)&out[((size_t)nb * COo + co) * HW + rem0 + px] = v;
    }
}

// ---------------- launch ----------------
extern "C" void kernel_launch(void* const* d_in, const int* in_sizes, int n_in,
                              void* d_out, int out_size) {
    const float* x      = (const float*)d_in[0];
    const float* w_off  = (const float*)d_in[1];
    const float* b_off  = (const float*)d_in[2];
    const float* weight = (const float*)d_in[3];
    const float* bias   = (const float*)d_in[4];
    float* out = (float*)d_out;

    static int attr_set = 0;
    if (!attr_set) {
        cudaFuncSetAttribute(k_fused, cudaFuncAttributeMaxDynamicSharedMemorySize, FUSED_SMEM);
        attr_set = 1;
    }

    k_prep<<<TP_BLOCKS + 216, 256>>>(x, weight, w_off);
    k_fused<<<NPIX / 128, 512, FUSED_SMEM>>>(b_off, bias, out);
}

// round 12
// speedup vs baseline: 1.1034x; 1.1034x over previous
#include <cuda_runtime.h>
#include <cuda_bf16.h>
#include <cstdint>

// Problem constants
#define Nn 8
#define Cc 64
#define Hh 96
#define Ww 96
#define COo 64
#define KK9 9
#define HW 9216           // 96*96
#define NPIX 73728        // 8*9216

// ---------------- scratch (device globals; no allocation allowed) ----------------
// x NHWC, tf32 bits, channels PERMUTED within 8-groups: pos = (c&~7) | ((c&3)<<1) | ((c>>2)&1)
__device__ __align__(16) uint32_t g_xtf[Nn * Hh * Ww * Cc];
// fragment-major weights, per-k-step uint4: [t][cog][kk][lane][nt][j]
__device__ __align__(16) uint32_t g_wtf[KK9 * 4 * 8 * 32 * 4];    // main conv (36864)
__device__ __align__(16) uint32_t g_wofff[KK9 * 2 * 8 * 32 * 4];  // off conv  (18432)

static __device__ __forceinline__ uint32_t f2tf32(float v) {
    uint32_t r;
    asm("cvt.rna.tf32.f32 %0, %1;" : "=r"(r) : "f"(v));
    return r;
}
static __device__ __forceinline__ uint32_t smem_u32(const void* p) {
    uint32_t a;
    asm("{ .reg .u64 t; cvta.to.shared.u64 t, %1; cvt.u32.u64 %0, t; }" : "=r"(a) : "l"(p));
    return a;
}
static __device__ __forceinline__ void mma_tf32(float* d, const uint32_t* a, const uint32_t* b) {
    asm volatile("mma.sync.aligned.m16n8k8.row.col.f32.tf32.tf32.f32 "
                 "{%0,%1,%2,%3}, {%4,%5,%6,%7}, {%8,%9}, {%0,%1,%2,%3};"
                 : "+f"(d[0]), "+f"(d[1]), "+f"(d[2]), "+f"(d[3])
                 : "r"(a[0]), "r"(a[1]), "r"(a[2]), "r"(a[3]), "r"(b[0]), "r"(b[1]));
}
#define CP_ASYNC16(dst, src, sz) \
    asm volatile("cp.async.cg.shared.global [%0], [%1], 16, %2;" :: "r"(dst), "l"(src), "r"(sz) : "memory")
#define CP_COMMIT() asm volatile("cp.async.commit_group;" ::: "memory")
#define CP_WAIT(n)  asm volatile("cp.async.wait_group %0;" :: "n"(n) : "memory")

// ---------------- kernel 0: x transpose (2 c-tiles/block) + weight prep, one launch ----------------
#define TP_BLOCKS 2304        // 3 wtiles * 768 (n*y)
__global__ void k_prep(const float* __restrict__ x,
                       const float* __restrict__ weight,
                       const float* __restrict__ w_off) {
    int b = blockIdx.x;
    int tid = threadIdx.x;
    if (b < TP_BLOCKS) {
        __shared__ float tile[2][32][33];
        int xb = (b % 3) * 32;
        int z = b / 3;
        int n = z / Hh;
        int y = z % Hh;
        int tx = tid & 31, ty = tid >> 5;
#pragma unroll
        for (int cb2 = 0; cb2 < 2; cb2++)
#pragma unroll
            for (int k = 0; k < 4; k++) {
                int c = cb2 * 32 + ty + k * 8;
                tile[cb2][ty + k * 8][tx] = x[((n * Cc + c) * Hh + y) * Ww + xb + tx];
            }
        __syncthreads();
#pragma unroll
        for (int cb2 = 0; cb2 < 2; cb2++) {
            int c = cb2 * 32 + tx;
            int s = (c & 56) | ((c & 3) << 1) | ((c >> 2) & 1);   // permuted position
#pragma unroll
            for (int k = 0; k < 4; k++) {
                int xo = xb + ty + k * 8;
                g_xtf[((n * Hh + y) * Ww + xo) * Cc + s] = f2tf32(tile[cb2][tx][ty + k * 8]);
            }
        }
    } else {
        int gidx = (b - TP_BLOCKS) * 256 + tid;
        if (gidx < KK9 * 4096) {
            int idx = gidx;
            int j = idx & 1;
            int nt = (idx >> 1) & 1;
            int lane = (idx >> 2) & 31;
            int kk = (idx >> 7) & 7;
            int cog = (idx >> 10) & 3;
            int t = idx >> 12;
            int co = cog * 16 + nt * 8 + (lane >> 2);
            int c = kk * 8 + (lane & 3) + 4 * j;
            g_wtf[idx] = f2tf32(weight[(co * Cc + c) * KK9 + t]);
        } else if (gidx < KK9 * 4096 + KK9 * 2048) {
            int idx = gidx - KK9 * 4096;
            int j = idx & 1;
            int nt = (idx >> 1) & 1;
            int lane = (idx >> 2) & 31;
            int kk = (idx >> 7) & 7;
            int cog = (idx >> 10) & 1;
            int t = idx >> 11;
            int ch = cog * 16 + nt * 8 + (lane >> 2);
            int c = kk * 8 + (lane & 3) + 4 * j;
            g_wofff[idx] = (ch < 27) ? f2tf32(w_off[(ch * Cc + c) * KK9 + t]) : 0u;
        }
    }
}

// ---------------- fused kernel: offconv (TC) -> metadata -> deform (TC) ----------------
#define A_STRIDE 72                            // 72 ≡ 8 (mod 32): conflict-free LDS.64 frags
#define O_STRIDE 132
#define BUFW (128 * A_STRIDE)                  // 9216 words per val buffer
#define SM_ENTW (2 * BUFW * 4)                 // 73728
#define SM_ENTB (SM_ENTW + 1152 * 16)          // 92160  (obase overlays here)
#define SM_ENTD (SM_ENTB + 1152 * 4)           // 96768
#define FUSED_SMEM (SM_ENTD + 1152 * 4)        // 101376

__global__ void __launch_bounds__(512, 2) k_fused(const float* __restrict__ b_off,
                                                  const float* __restrict__ bias,
                                                  float* __restrict__ out) {
    extern __shared__ char base[];
    uint32_t* valS = (uint32_t*)base;                // [2][128][72]
    float4*   entW = (float4*)(base + SM_ENTW);
    int*      entB = (int*)(base + SM_ENTB);
    int*      entD = (int*)(base + SM_ENTD);
    int*      obase = entB;                          // overlay (dead before entB written)
    float*    offmS = (float*)base;                  // [128][28] overlay (written after phase A)
    float*    outS = (float*)base;                   // epilogue overlay [64co][132]
    uint32_t  valS_sm = smem_u32(valS);
    const float* xtf = (const float*)g_xtf;

    int tid = threadIdx.x;
    int wid = tid >> 5;
    int lane = tid & 31;
    int pix0 = blockIdx.x * 128;
    int nb = pix0 / HW;
    int rem0 = pix0 % HW;
    int lg = lane >> 2;
    int lt = lane & 3;

    // ============ phase A: offset conv (128pix x 32ch, warp tile 16pix x 16ch) ============
    for (int e = tid; e < KK9 * 128; e += 512) {
        int t = e >> 7;
        int pl = e & 127;
        int rem = rem0 + pl;
        int yy = rem / Ww + t / 3 - 1;
        int xx = rem % Ww + t % 3 - 1;
        obase[e] = ((unsigned)yy < Hh && (unsigned)xx < Ww)
                 ? ((nb * Hh + yy) * Ww + xx) * Cc : -1;
    }
    __syncthreads();

    int wmA = (wid & 7) * 16;     // warp pixel base (phase A)
    int cogA = wid >> 3;          // ch group (16 ch)

    float accA[2][4];
#pragma unroll
    for (int nt = 0; nt < 2; nt++)
#pragma unroll
        for (int r = 0; r < 4; r++) accA[nt][r] = 0.f;

    auto fillA = [&](int tt, int b) {
        uint32_t dbase = valS_sm + b * (BUFW * 4);
#pragma unroll
        for (int j = 0; j < 4; j++) {
            int idx = tid + j * 512;
            int pl = idx >> 4;
            int c4 = (idx & 15) << 2;
            int gb = obase[tt * 128 + pl];
            const uint32_t* src = &g_xtf[(gb < 0 ? 0 : gb) + c4];
            CP_ASYNC16(dbase + (pl * A_STRIDE + c4) * 4, src, (gb < 0) ? 0 : 16);
        }
        CP_COMMIT();
    };

    fillA(0, 0);
    for (int t = 0; t < KK9; t++) {
        CP_WAIT(0);
        __syncthreads();                 // fill(t) complete everywhere; mma(t-1) done everywhere
        if (t < KK9 - 1) fillA(t + 1, (t + 1) & 1);
        const uint32_t* cur = valS + (t & 1) * BUFW;
#pragma unroll
        for (int kk = 0; kk < 8; kk++) {
            int k0 = kk * 8 + 2 * lt;
            uint2 p0 = *(const uint2*)&cur[(wmA + lg) * A_STRIDE + k0];
            uint2 p1 = *(const uint2*)&cur[(wmA + 8 + lg) * A_STRIDE + k0];
            uint32_t a[4] = {p0.x, p1.x, p0.y, p1.y};
            uint4 bv = ((const uint4*)&g_wofff[((t * 2 + cogA) * 8 + kk) * 128])[lane];
            uint32_t b0[2] = {bv.x, bv.y};
            uint32_t b1[2] = {bv.z, bv.w};
            mma_tf32(accA[0], a, b0);
            mma_tf32(accA[1], a, b1);
        }
    }
    __syncthreads();                     // all mma done before offmS overlays buf0

    // phase A epilogue -> offmS
#pragma unroll
    for (int nt = 0; nt < 2; nt++)
#pragma unroll
        for (int r = 0; r < 4; r++) {
            int pix = wmA + ((r >> 1) << 3) + lg;
            int ch = cogA * 16 + nt * 8 + 2 * lt + (r & 1);
            if (ch < 27) {
                float v = accA[nt][r] + __ldg(&b_off[ch]);
                if (ch >= 18) v = 1.f / (1.f + __expf(-v));
                offmS[pix * 28 + ch] = v;
            }
        }
    __syncthreads();

    // ============ metadata: bilinear coefficients for all 9 taps ============
    for (int e = tid; e < KK9 * 128; e += 512) {
        int t = e >> 7;
        int pl = e & 127;
        int rem = rem0 + pl;
        int y = rem / Ww;
        int x = rem % Ww;
        float dy = offmS[pl * 28 + 2 * t];
        float dx = offmS[pl * 28 + 2 * t + 1];
        float m = offmS[pl * 28 + 18 + t];
        int ky = t / 3, kx = t % 3;
        float py = (float)(y + ky - 1) + dy;
        float px = (float)(x + kx - 1) + dx;
        float fy = floorf(py), fx = floorf(px);
        float ly = py - fy, lx = px - fx;
        int iy = (int)fy, ix = (int)fx;
        float hy0 = (iy >= 0 && iy < Hh) ? (1.f - ly) : 0.f;
        float hy1 = (iy >= -1 && iy < Hh - 1) ? ly : 0.f;
        float hx0 = (ix >= 0 && ix < Ww) ? (1.f - lx) : 0.f;
        float hx1 = (ix >= -1 && ix < Ww - 1) ? lx : 0.f;
        int iyc = min(max(iy, 0), Hh - 1);
        int ixc = min(max(ix, 0), Ww - 1);
        int ddy = (iy >= 0 && iy < Hh - 1) ? Ww * Cc : 0;
        int ddx = (ix >= 0 && ix < Ww - 1) ? Cc : 0;
        entB[e] = ((nb * Hh + iyc) * Ww + ixc) * Cc;   // overwrites obase (dead)
        entD[e] = ddx | (ddy << 16);
        entW[e] = make_float4(hy0 * hx0 * m, hy0 * hx1 * m, hy1 * hx0 * m, hy1 * hx1 * m);
    }

    // ============ phase B: deform (128pix x 64co, warp tile 32pix x 16co) ============
    int wm = (wid & 3) * 32;
    int cog = wid >> 2;
    int c4 = (tid & 15) << 2;     // gather channel position (float4 granule)
    int q4 = tid >> 4;            // gather pixel phase (0..31)

    float acc[2][2][4];
#pragma unroll
    for (int mt = 0; mt < 2; mt++)
#pragma unroll
        for (int nt = 0; nt < 2; nt++)
#pragma unroll
            for (int r = 0; r < 4; r++) acc[mt][nt][r] = 0.f;
    __syncthreads();              // metadata visible; offmS/valS free

    // vectorized gather of tap -> buffer (short live ranges; MLP across iterations)
    auto gatherB = [&](int tt, uint32_t* dst) {
        int tb = tt * 128;
#pragma unroll
        for (int s = 0; s < 4; s++) {
            int pl = s * 32 + q4;
            int e = tb + pl;
            float4 w = entW[e];
            int gbase = entB[e] + c4;
            int dd = entD[e];
            int ddx = dd & 0xffff;
            int ddy = dd >> 16;
            float4 v00 = *(const float4*)&xtf[gbase];
            float4 v01 = *(const float4*)&xtf[gbase + ddx];
            float4 v10 = *(const float4*)&xtf[gbase + ddy];
            float4 v11 = *(const float4*)&xtf[gbase + ddy + ddx];
            uint4 o;
            o.x = f2tf32(w.x * v00.x + w.y * v01.x + w.z * v10.x + w.w * v11.x);
            o.y = f2tf32(w.x * v00.y + w.y * v01.y + w.z * v10.y + w.w * v11.y);
            o.z = f2tf32(w.x * v00.z + w.y * v01.z + w.z * v10.z + w.w * v11.z);
            o.w = f2tf32(w.x * v00.w + w.y * v01.w + w.z * v10.w + w.w * v11.w);
            *(uint4*)&dst[pl * A_STRIDE + c4] = o;
        }
    };

    // prologue gather: tap 0 -> buf 0
    gatherB(0, valS);
    __syncthreads();

    for (int t = 0; t < KK9; t++) {
        const uint32_t* cur = valS + (t & 1) * BUFW;
#pragma unroll
        for (int kk = 0; kk < 8; kk++) {
            int k0 = kk * 8 + 2 * lt;
            uint32_t a[2][4];
#pragma unroll
            for (int mt = 0; mt < 2; mt++) {
                uint2 p0 = *(const uint2*)&cur[(wm + mt * 16 + lg) * A_STRIDE + k0];
                uint2 p1 = *(const uint2*)&cur[(wm + mt * 16 + 8 + lg) * A_STRIDE + k0];
                a[mt][0] = p0.x; a[mt][1] = p1.x; a[mt][2] = p0.y; a[mt][3] = p1.y;
            }
            uint4 bv = ((const uint4*)&g_wtf[((t * 4 + cog) * 8 + kk) * 128])[lane];
            uint32_t b0[2] = {bv.x, bv.y};
            uint32_t b1[2] = {bv.z, bv.w};
#pragma unroll
            for (int mt = 0; mt < 2; mt++) {
                mma_tf32(acc[mt][0], a[mt], b0);
                mma_tf32(acc[mt][1], a[mt], b1);
            }
        }
        if (t < KK9 - 1) {
            gatherB(t + 1, valS + ((t + 1) & 1) * BUFW);
        }
        __syncthreads();
    }

    // epilogue: fragments -> smem [co][pix] -> coalesced NCHW stores
#pragma unroll
    for (int mt = 0; mt < 2; mt++)
#pragma unroll
        for (int nt = 0; nt < 2; nt++)
#pragma unroll
            for (int r = 0; r < 4; r++) {
                int pix = wm + mt * 16 + ((r >> 1) << 3) + lg;
                int co = cog * 16 + nt * 8 + 2 * lt + (r & 1);
                outS[co * O_STRIDE + pix] = acc[mt][nt][r];
            }
    __syncthreads();

#pragma unroll
    for (int i = 0; i < 4; i++) {
        int co = i * 16 + wid;
        int px = lane * 4;
        float4 v = *(const float4*)&outS[co * O_STRIDE + px];
        float bv = __ldg(&bias[co]);
        v.x += bv; v.y += bv; v.z += bv; v.w += bv;
        *(float4*)&out[((size_t)nb * COo + co) * HW + rem0 + px] = v;
    }
}

// ---------------- launch ----------------
extern "C" void kernel_launch(void* const* d_in, const int* in_sizes, int n_in,
                              void* d_out, int out_size) {
    const float* x      = (const float*)d_in[0];
    const float* w_off  = (const float*)d_in[1];
    const float* b_off  = (const float*)d_in[2];
    const float* weight = (const float*)d_in[3];
    const float* bias   = (const float*)d_in[4];
    float* out = (float*)d_out;

    static int attr_set = 0;
    if (!attr_set) {
        cudaFuncSetAttribute(k_fused, cudaFuncAttributeMaxDynamicSharedMemorySize, FUSED_SMEM);
        attr_set = 1;
    }

    k_prep<<<TP_BLOCKS + 216, 256>>>(x, weight, w_off);
    k_fused<<<NPIX / 128, 512, FUSED_SMEM>>>(b_off, bias, out);
}

// round 13
// speedup vs baseline: 1.1231x; 1.0178x over previous
#include <cuda_runtime.h>
#include <cuda_bf16.h>
#include <cstdint>

// Problem constants
#define Nn 8
#define Cc 64
#define Hh 96
#define Ww 96
#define COo 64
#define KK9 9
#define HW 9216           // 96*96
#define NPIX 73728        // 8*9216

// ---------------- scratch (device globals; no allocation allowed) ----------------
// x NHWC, tf32 bits, channels PERMUTED for paired-k-step LDS.128 fragments:
// c -> pos = (kk>>1)*16 + lt*4 + (kk&1)*2 + j   (kk=c>>3, lt=c&3, j=(c>>2)&1)
__device__ __align__(16) uint32_t g_xtf[Nn * Hh * Ww * Cc];
// fragment-major weights, word layout [t][cog][kk][lane][nt][j]
__device__ __align__(16) uint32_t g_wtf[KK9 * 4 * 8 * 32 * 4];    // main conv (36864)
__device__ __align__(16) uint32_t g_wofff[KK9 * 2 * 8 * 32 * 4];  // off conv  (18432)

static __device__ __forceinline__ uint32_t f2tf32(float v) {
    uint32_t r;
    asm("cvt.rna.tf32.f32 %0, %1;" : "=r"(r) : "f"(v));
    return r;
}
static __device__ __forceinline__ uint32_t smem_u32(const void* p) {
    uint32_t a;
    asm("{ .reg .u64 t; cvta.to.shared.u64 t, %1; cvt.u32.u64 %0, t; }" : "=r"(a) : "l"(p));
    return a;
}
static __device__ __forceinline__ void mma_tf32(float* d, const uint32_t* a, const uint32_t* b) {
    asm volatile("mma.sync.aligned.m16n8k8.row.col.f32.tf32.tf32.f32 "
                 "{%0,%1,%2,%3}, {%4,%5,%6,%7}, {%8,%9}, {%0,%1,%2,%3};"
                 : "+f"(d[0]), "+f"(d[1]), "+f"(d[2]), "+f"(d[3])
                 : "r"(a[0]), "r"(a[1]), "r"(a[2]), "r"(a[3]), "r"(b[0]), "r"(b[1]));
}
#define CP_ASYNC16(dst, src, sz) \
    asm volatile("cp.async.cg.shared.global [%0], [%1], 16, %2;" :: "r"(dst), "l"(src), "r"(sz) : "memory")
#define CP_COMMIT() asm volatile("cp.async.commit_group;" ::: "memory")
#define CP_WAIT(n)  asm volatile("cp.async.wait_group %0;" :: "n"(n) : "memory")

// ---------------- kernel 0: x transpose (2 c-tiles/block) + weight prep, one launch ----------------
#define TP_BLOCKS 2304        // 3 wtiles * 768 (n*y)
__global__ void k_prep(const float* __restrict__ x,
                       const float* __restrict__ weight,
                       const float* __restrict__ w_off) {
    int b = blockIdx.x;
    int tid = threadIdx.x;
    if (b < TP_BLOCKS) {
        __shared__ float tile[2][32][33];
        int xb = (b % 3) * 32;
        int z = b / 3;
        int n = z / Hh;
        int y = z % Hh;
        int tx = tid & 31, ty = tid >> 5;
#pragma unroll
        for (int cb2 = 0; cb2 < 2; cb2++)
#pragma unroll
            for (int k = 0; k < 4; k++) {
                int c = cb2 * 32 + ty + k * 8;
                tile[cb2][ty + k * 8][tx] = x[((n * Cc + c) * Hh + y) * Ww + xb + tx];
            }
        __syncthreads();
#pragma unroll
        for (int cb2 = 0; cb2 < 2; cb2++) {
            int c = cb2 * 32 + tx;
            int kk = c >> 3, lt = c & 3, j = (c >> 2) & 1;
            int s = (kk >> 1) * 16 + lt * 4 + (kk & 1) * 2 + j;   // paired-k permutation
#pragma unroll
            for (int k = 0; k < 4; k++) {
                int xo = xb + ty + k * 8;
                g_xtf[((n * Hh + y) * Ww + xo) * Cc + s] = f2tf32(tile[cb2][tx][ty + k * 8]);
            }
        }
    } else {
        int gidx = (b - TP_BLOCKS) * 256 + tid;
        if (gidx < KK9 * 4096) {
            int idx = gidx;
            int j = idx & 1;
            int nt = (idx >> 1) & 1;
            int lane = (idx >> 2) & 31;
            int kk = (idx >> 7) & 7;
            int cog = (idx >> 10) & 3;
            int t = idx >> 12;
            int co = cog * 16 + nt * 8 + (lane >> 2);
            int c = kk * 8 + (lane & 3) + 4 * j;
            g_wtf[idx] = f2tf32(weight[(co * Cc + c) * KK9 + t]);
        } else if (gidx < KK9 * 4096 + KK9 * 2048) {
            int idx = gidx - KK9 * 4096;
            int j = idx & 1;
            int nt = (idx >> 1) & 1;
            int lane = (idx >> 2) & 31;
            int kk = (idx >> 7) & 7;
            int cog = (idx >> 10) & 1;
            int t = idx >> 11;
            int ch = cog * 16 + nt * 8 + (lane >> 2);
            int c = kk * 8 + (lane & 3) + 4 * j;
            g_wofff[idx] = (ch < 27) ? f2tf32(w_off[(ch * Cc + c) * KK9 + t]) : 0u;
        }
    }
}

// ---------------- fused kernel: offconv (TC) -> metadata -> deform (TC) ----------------
#define A_STRIDE 80                            // 80 ≡ 16 (mod 32): conflict-free LDS.128 frags
#define O_STRIDE 132
#define BUFW (128 * A_STRIDE)                  // 10240 words per val buffer
#define SM_ENTW (2 * BUFW * 4)                 // 81920
#define SM_ENTB (SM_ENTW + 1152 * 16)          // 100352 (obase overlays here)
#define SM_ENTD (SM_ENTB + 1152 * 4)           // 104960
#define FUSED_SMEM (SM_ENTD + 1152 * 4)        // 109568

__global__ void __launch_bounds__(512, 2) k_fused(const float* __restrict__ b_off,
                                                  const float* __restrict__ bias,
                                                  float* __restrict__ out) {
    extern __shared__ char base[];
    uint32_t* valS = (uint32_t*)base;                // [2][128][80]
    float4*   entW = (float4*)(base + SM_ENTW);
    int*      entB = (int*)(base + SM_ENTB);
    int*      entD = (int*)(base + SM_ENTD);
    int*      obase = entB;                          // overlay (dead before entB written)
    float*    offmS = (float*)base;                  // [128][28] overlay (written after phase A)
    float*    outS = (float*)base;                   // epilogue overlay [64co][132]
    uint32_t  valS_sm = smem_u32(valS);
    const float* xtf = (const float*)g_xtf;

    int tid = threadIdx.x;
    int wid = tid >> 5;
    int lane = tid & 31;
    int pix0 = blockIdx.x * 128;
    int nb = pix0 / HW;
    int rem0 = pix0 % HW;
    int lg = lane >> 2;
    int lt = lane & 3;

    // ============ phase A: offset conv (128pix x 32ch, warp tile 16pix x 16ch) ============
    for (int e = tid; e < KK9 * 128; e += 512) {
        int t = e >> 7;
        int pl = e & 127;
        int rem = rem0 + pl;
        int yy = rem / Ww + t / 3 - 1;
        int xx = rem % Ww + t % 3 - 1;
        obase[e] = ((unsigned)yy < Hh && (unsigned)xx < Ww)
                 ? ((nb * Hh + yy) * Ww + xx) * Cc : -1;
    }
    __syncthreads();

    int wmA = (wid & 7) * 16;     // warp pixel base (phase A)
    int cogA = wid >> 3;          // ch group (16 ch)

    float accA[2][4];
#pragma unroll
    for (int nt = 0; nt < 2; nt++)
#pragma unroll
        for (int r = 0; r < 4; r++) accA[nt][r] = 0.f;

    auto fillA = [&](int tt, int b) {
        uint32_t dbase = valS_sm + b * (BUFW * 4);
#pragma unroll
        for (int j = 0; j < 4; j++) {
            int idx = tid + j * 512;
            int pl = idx >> 4;
            int c4 = (idx & 15) << 2;
            int gb = obase[tt * 128 + pl];
            const uint32_t* src = &g_xtf[(gb < 0 ? 0 : gb) + c4];
            CP_ASYNC16(dbase + (pl * A_STRIDE + c4) * 4, src, (gb < 0) ? 0 : 16);
        }
        CP_COMMIT();
    };

    fillA(0, 0);
    for (int t = 0; t < KK9; t++) {
        CP_WAIT(0);
        __syncthreads();                 // fill(t) complete everywhere; mma(t-1) done everywhere
        if (t < KK9 - 1) fillA(t + 1, (t + 1) & 1);
        const uint32_t* cur = valS + (t & 1) * BUFW;
#pragma unroll
        for (int s2 = 0; s2 < 4; s2++) {
            int kb = s2 * 16 + lt * 4;
            uint4 q0 = *(const uint4*)&cur[(wmA + lg) * A_STRIDE + kb];
            uint4 q1 = *(const uint4*)&cur[(wmA + 8 + lg) * A_STRIDE + kb];
            uint4 bv0 = ((const uint4*)&g_wofff[((t * 2 + cogA) * 8 + 2 * s2) * 128])[lane];
            uint4 bv1 = ((const uint4*)&g_wofff[((t * 2 + cogA) * 8 + 2 * s2 + 1) * 128])[lane];
            uint32_t a0[4] = {q0.x, q1.x, q0.y, q1.y};       // k-step 2*s2
            uint32_t a1[4] = {q0.z, q1.z, q0.w, q1.w};       // k-step 2*s2+1
            uint32_t b00[2] = {bv0.x, bv0.y}, b01[2] = {bv0.z, bv0.w};
            uint32_t b10[2] = {bv1.x, bv1.y}, b11[2] = {bv1.z, bv1.w};
            mma_tf32(accA[0], a0, b00);
            mma_tf32(accA[1], a0, b01);
            mma_tf32(accA[0], a1, b10);
            mma_tf32(accA[1], a1, b11);
        }
    }
    __syncthreads();                     // all mma done before offmS overlays buf0

    // phase A epilogue -> offmS
#pragma unroll
    for (int nt = 0; nt < 2; nt++)
#pragma unroll
        for (int r = 0; r < 4; r++) {
            int pix = wmA + ((r >> 1) << 3) + lg;
            int ch = cogA * 16 + nt * 8 + 2 * lt + (r & 1);
            if (ch < 27) {
                float v = accA[nt][r] + __ldg(&b_off[ch]);
                if (ch >= 18) v = 1.f / (1.f + __expf(-v));
                offmS[pix * 28 + ch] = v;
            }
        }
    __syncthreads();

    // ============ metadata: bilinear coefficients for all 9 taps ============
    for (int e = tid; e < KK9 * 128; e += 512) {
        int t = e >> 7;
        int pl = e & 127;
        int rem = rem0 + pl;
        int y = rem / Ww;
        int x = rem % Ww;
        float dy = offmS[pl * 28 + 2 * t];
        float dx = offmS[pl * 28 + 2 * t + 1];
        float m = offmS[pl * 28 + 18 + t];
        int ky = t / 3, kx = t % 3;
        float py = (float)(y + ky - 1) + dy;
        float px = (float)(x + kx - 1) + dx;
        float fy = floorf(py), fx = floorf(px);
        float ly = py - fy, lx = px - fx;
        int iy = (int)fy, ix = (int)fx;
        float hy0 = (iy >= 0 && iy < Hh) ? (1.f - ly) : 0.f;
        float hy1 = (iy >= -1 && iy < Hh - 1) ? ly : 0.f;
        float hx0 = (ix >= 0 && ix < Ww) ? (1.f - lx) : 0.f;
        float hx1 = (ix >= -1 && ix < Ww - 1) ? lx : 0.f;
        int iyc = min(max(iy, 0), Hh - 1);
        int ixc = min(max(ix, 0), Ww - 1);
        int ddy = (iy >= 0 && iy < Hh - 1) ? Ww * Cc : 0;
        int ddx = (ix >= 0 && ix < Ww - 1) ? Cc : 0;
        entB[e] = ((nb * Hh + iyc) * Ww + ixc) * Cc;   // overwrites obase (dead)
        entD[e] = ddx | (ddy << 16);
        entW[e] = make_float4(hy0 * hx0 * m, hy0 * hx1 * m, hy1 * hx0 * m, hy1 * hx1 * m);
    }

    // ============ phase B: deform (128pix x 64co, warp tile 32pix x 16co) ============
    int wm = (wid & 3) * 32;
    int cog = wid >> 2;
    int c4 = (tid & 15) << 2;     // gather channel position (float4 granule)
    int q4 = tid >> 4;            // gather pixel phase (0..31)

    float acc[2][2][4];
#pragma unroll
    for (int mt = 0; mt < 2; mt++)
#pragma unroll
        for (int nt = 0; nt < 2; nt++)
#pragma unroll
            for (int r = 0; r < 4; r++) acc[mt][nt][r] = 0.f;
    __syncthreads();              // metadata visible; offmS/valS free

    // vectorized gather of tap -> buffer (short live ranges; MLP across iterations)
    auto gatherB = [&](int tt, uint32_t* dst) {
        int tb = tt * 128;
#pragma unroll
        for (int s = 0; s < 4; s++) {
            int pl = s * 32 + q4;
            int e = tb + pl;
            float4 w = entW[e];
            int gbase = entB[e] + c4;
            int dd = entD[e];
            int ddx = dd & 0xffff;
            int ddy = dd >> 16;
            float4 v00 = *(const float4*)&xtf[gbase];
            float4 v01 = *(const float4*)&xtf[gbase + ddx];
            float4 v10 = *(const float4*)&xtf[gbase + ddy];
            float4 v11 = *(const float4*)&xtf[gbase + ddy + ddx];
            uint4 o;
            o.x = f2tf32(w.x * v00.x + w.y * v01.x + w.z * v10.x + w.w * v11.x);
            o.y = f2tf32(w.x * v00.y + w.y * v01.y + w.z * v10.y + w.w * v11.y);
            o.z = f2tf32(w.x * v00.z + w.y * v01.z + w.z * v10.z + w.w * v11.z);
            o.w = f2tf32(w.x * v00.w + w.y * v01.w + w.z * v10.w + w.w * v11.w);
            *(uint4*)&dst[pl * A_STRIDE + c4] = o;
        }
    };

    // prologue gather: tap 0 -> buf 0
    gatherB(0, valS);
    __syncthreads();

    for (int t = 0; t < KK9; t++) {
        const uint32_t* cur = valS + (t & 1) * BUFW;
#pragma unroll
        for (int s2 = 0; s2 < 4; s2++) {
            int kb = s2 * 16 + lt * 4;
            uint4 q[2][2];
#pragma unroll
            for (int mt = 0; mt < 2; mt++) {
                q[mt][0] = *(const uint4*)&cur[(wm + mt * 16 + lg) * A_STRIDE + kb];
                q[mt][1] = *(const uint4*)&cur[(wm + mt * 16 + 8 + lg) * A_STRIDE + kb];
            }
            uint4 bv0 = ((const uint4*)&g_wtf[((t * 4 + cog) * 8 + 2 * s2) * 128])[lane];
            uint4 bv1 = ((const uint4*)&g_wtf[((t * 4 + cog) * 8 + 2 * s2 + 1) * 128])[lane];
            uint32_t b00[2] = {bv0.x, bv0.y}, b01[2] = {bv0.z, bv0.w};
            uint32_t b10[2] = {bv1.x, bv1.y}, b11[2] = {bv1.z, bv1.w};
#pragma unroll
            for (int mt = 0; mt < 2; mt++) {
                uint32_t a0[4] = {q[mt][0].x, q[mt][1].x, q[mt][0].y, q[mt][1].y};
                uint32_t a1[4] = {q[mt][0].z, q[mt][1].z, q[mt][0].w, q[mt][1].w};
                mma_tf32(acc[mt][0], a0, b00);
                mma_tf32(acc[mt][1], a0, b01);
                mma_tf32(acc[mt][0], a1, b10);
                mma_tf32(acc[mt][1], a1, b11);
            }
        }
        if (t < KK9 - 1) {
            gatherB(t + 1, valS + ((t + 1) & 1) * BUFW);
        }
        __syncthreads();
    }

    // epilogue: fragments -> smem [co][pix] -> coalesced NCHW stores
#pragma unroll
    for (int mt = 0; mt < 2; mt++)
#pragma unroll
        for (int nt = 0; nt < 2; nt++)
#pragma unroll
            for (int r = 0; r < 4; r++) {
                int pix = wm + mt * 16 + ((r >> 1) << 3) + lg;
                int co = cog * 16 + nt * 8 + 2 * lt + (r & 1);
                outS[co * O_STRIDE + pix] = acc[mt][nt][r];
            }
    __syncthreads();

#pragma unroll
    for (int i = 0; i < 4; i++) {
        int co = i * 16 + wid;
        int px = lane * 4;
        float4 v = *(const float4*)&outS[co * O_STRIDE + px];
        float bv = __ldg(&bias[co]);
        v.x += bv; v.y += bv; v.z += bv; v.w += bv;
        *(float4*)&out[((size_t)nb * COo + co) * HW + rem0 + px] = v;
    }
}

// ---------------- launch ----------------
extern "C" void kernel_launch(void* const* d_in, const int* in_sizes, int n_in,
                              void* d_out, int out_size) {
    const float* x      = (const float*)d_in[0];
    const float* w_off  = (const float*)d_in[1];
    const float* b_off  = (const float*)d_in[2];
    const float* weight = (const float*)d_in[3];
    const float* bias   = (const float*)d_in[4];
    float* out = (float*)d_out;

    static int attr_set = 0;
    if (!attr_set) {
        cudaFuncSetAttribute(k_fused, cudaFuncAttributeMaxDynamicSharedMemorySize, FUSED_SMEM);
        attr_set = 1;
    }

    k_prep<<<TP_BLOCKS + 216, 256>>>(x, weight, w_off);
    k_fused<<<NPIX / 128, 512, FUSED_SMEM>>>(b_off, bias, out);
}

// round 16
// speedup vs baseline: 1.1428x; 1.0176x over previous
#include <cuda_runtime.h>
#include <cuda_bf16.h>
#include <cstdint>

// Problem constants
#define Nn 8
#define Cc 64
#define Hh 96
#define Ww 96
#define COo 64
#define KK9 9
#define HW 9216           // 96*96
#define NPIX 73728        // 8*9216

// ---------------- scratch (device globals; no allocation allowed) ----------------
// x NHWC, tf32 bits, channels PERMUTED for paired-k-step LDS.128 fragments:
// c -> pos = (kk>>1)*16 + lt*4 + (kk&1)*2 + j   (kk=c>>3, lt=c&3, j=(c>>2)&1)
__device__ __align__(16) uint32_t g_xtf[Nn * Hh * Ww * Cc];
// fragment-major weights, word layout [t][cog][kk][lane][nt][j]
__device__ __align__(16) uint32_t g_wtf[KK9 * 4 * 8 * 32 * 4];    // main conv (36864)
__device__ __align__(16) uint32_t g_wofff[KK9 * 2 * 8 * 32 * 4];  // off conv  (18432)

static __device__ __forceinline__ uint32_t f2tf32(float v) {
    uint32_t r;
    asm("cvt.rna.tf32.f32 %0, %1;" : "=r"(r) : "f"(v));
    return r;
}
static __device__ __forceinline__ uint32_t smem_u32(const void* p) {
    uint32_t a;
    asm("{ .reg .u64 t; cvta.to.shared.u64 t, %1; cvt.u32.u64 %0, t; }" : "=r"(a) : "l"(p));
    return a;
}
static __device__ __forceinline__ void mma_tf32(float* d, const uint32_t* a, const uint32_t* b) {
    asm volatile("mma.sync.aligned.m16n8k8.row.col.f32.tf32.tf32.f32 "
                 "{%0,%1,%2,%3}, {%4,%5,%6,%7}, {%8,%9}, {%0,%1,%2,%3};"
                 : "+f"(d[0]), "+f"(d[1]), "+f"(d[2]), "+f"(d[3])
                 : "r"(a[0]), "r"(a[1]), "r"(a[2]), "r"(a[3]), "r"(b[0]), "r"(b[1]));
}
#define CP_ASYNC16(dst, src, sz) \
    asm volatile("cp.async.cg.shared.global [%0], [%1], 16, %2;" :: "r"(dst), "l"(src), "r"(sz) : "memory")
#define CP_COMMIT() asm volatile("cp.async.commit_group;" ::: "memory")
#define CP_WAIT(n)  asm volatile("cp.async.wait_group %0;" :: "n"(n) : "memory")

// ---------------- kernel 0: x transpose (2 c-tiles/block) + weight prep, one launch ----------------
#define TP_BLOCKS 2304        // 3 wtiles * 768 (n*y)
__global__ void k_prep(const float* __restrict__ x,
                       const float* __restrict__ weight,
                       const float* __restrict__ w_off) {
    int b = blockIdx.x;
    int tid = threadIdx.x;
    if (b < TP_BLOCKS) {
        __shared__ float tile[2][32][33];
        int xb = (b % 3) * 32;
        int z = b / 3;
        int n = z / Hh;
        int y = z % Hh;
        int tx = tid & 31, ty = tid >> 5;
#pragma unroll
        for (int cb2 = 0; cb2 < 2; cb2++)
#pragma unroll
            for (int k = 0; k < 4; k++) {
                int c = cb2 * 32 + ty + k * 8;
                tile[cb2][ty + k * 8][tx] = x[((n * Cc + c) * Hh + y) * Ww + xb + tx];
            }
        __syncthreads();
#pragma unroll
        for (int cb2 = 0; cb2 < 2; cb2++) {
            int c = cb2 * 32 + tx;
            int kk = c >> 3, lt = c & 3, j = (c >> 2) & 1;
            int s = (kk >> 1) * 16 + lt * 4 + (kk & 1) * 2 + j;   // paired-k permutation
#pragma unroll
            for (int k = 0; k < 4; k++) {
                int xo = xb + ty + k * 8;
                g_xtf[((n * Hh + y) * Ww + xo) * Cc + s] = f2tf32(tile[cb2][tx][ty + k * 8]);
            }
        }
    } else {
        int gidx = (b - TP_BLOCKS) * 256 + tid;
        if (gidx < KK9 * 4096) {
            int idx = gidx;
            int j = idx & 1;
            int nt = (idx >> 1) & 1;
            int lane = (idx >> 2) & 31;
            int kk = (idx >> 7) & 7;
            int cog = (idx >> 10) & 3;
            int t = idx >> 12;
            int co = cog * 16 + nt * 8 + (lane >> 2);
            int c = kk * 8 + (lane & 3) + 4 * j;
            g_wtf[idx] = f2tf32(weight[(co * Cc + c) * KK9 + t]);
        } else if (gidx < KK9 * 4096 + KK9 * 2048) {
            int idx = gidx - KK9 * 4096;
            int j = idx & 1;
            int nt = (idx >> 1) & 1;
            int lane = (idx >> 2) & 31;
            int kk = (idx >> 7) & 7;
            int cog = (idx >> 10) & 1;
            int t = idx >> 11;
            int ch = cog * 16 + nt * 8 + (lane >> 2);
            int c = kk * 8 + (lane & 3) + 4 * j;
            g_wofff[idx] = (ch < 27) ? f2tf32(w_off[(ch * Cc + c) * KK9 + t]) : 0u;
        }
    }
}

// ---------------- fused kernel: offconv (TC) -> metadata -> deform (TC) ----------------
// 256 threads / 8 warps per CTA; 128-pixel tile; warp tiles 32x16 (A) / 32x32 (B phase).
#define A_STRIDE 80                            // 80 ≡ 16 (mod 32): conflict-free LDS.128 frags
#define O_STRIDE 132
#define BUFW (128 * A_STRIDE)                  // 10240 words per val buffer
#define SM_ENTW (2 * BUFW * 4)                 // 81920
#define SM_ENTB (SM_ENTW + 1152 * 16)          // 100352 (obase overlays here)
#define SM_ENTD (SM_ENTB + 1152 * 4)           // 104960
#define FUSED_SMEM (SM_ENTD + 1152 * 4)        // 109568

__global__ void __launch_bounds__(256, 2) k_fused(const float* __restrict__ b_off,
                                                  const float* __restrict__ bias,
                                                  float* __restrict__ out) {
    extern __shared__ char base[];
    uint32_t* valS = (uint32_t*)base;                // [2][128][80]
    float4*   entW = (float4*)(base + SM_ENTW);
    int*      entB = (int*)(base + SM_ENTB);
    int*      entD = (int*)(base + SM_ENTD);
    int*      obase = entB;                          // overlay (dead before entB written)
    float*    offmS = (float*)base;                  // [128][28] overlay (written after phase A)
    float*    outS = (float*)base;                   // epilogue overlay [64co][132]
    uint32_t  valS_sm = smem_u32(valS);
    const float* xtf = (const float*)g_xtf;

    int tid = threadIdx.x;
    int wid = tid >> 5;           // 0..7
    int lane = tid & 31;
    int pix0 = blockIdx.x * 128;
    int nb = pix0 / HW;
    int rem0 = pix0 % HW;
    int lg = lane >> 2;
    int lt = lane & 3;

    // ============ phase A: offset conv (128pix x 32ch, warp tile 32pix x 16ch) ============
    for (int e = tid; e < KK9 * 128; e += 256) {
        int t = e / 128;
        int pl = e & 127;
        int rem = rem0 + pl;
        int yy = rem / Ww + t / 3 - 1;
        int xx = rem % Ww + t % 3 - 1;
        obase[e] = ((unsigned)yy < Hh && (unsigned)xx < Ww)
                 ? ((nb * Hh + yy) * Ww + xx) * Cc : -1;
    }
    __syncthreads();

    int wm = (wid & 3) * 32;      // warp pixel base (both phases)
    int cogA = wid >> 2;          // ch group (16 ch), 0..1

    float accA[2][2][4];
#pragma unroll
    for (int mt = 0; mt < 2; mt++)
#pragma unroll
        for (int nt = 0; nt < 2; nt++)
#pragma unroll
            for (int r = 0; r < 4; r++) accA[mt][nt][r] = 0.f;

    auto fillA = [&](int tt, int b) {
        uint32_t dbase = valS_sm + b * (BUFW * 4);
#pragma unroll
        for (int j = 0; j < 8; j++) {
            int idx = tid + j * 256;
            int pl = idx >> 4;
            int c4 = (idx & 15) << 2;
            int gb = obase[tt * 128 + pl];
            const uint32_t* src = &g_xtf[(gb < 0 ? 0 : gb) + c4];
            CP_ASYNC16(dbase + (pl * A_STRIDE + c4) * 4, src, (gb < 0) ? 0 : 16);
        }
        CP_COMMIT();
    };

    fillA(0, 0);
    for (int t = 0; t < KK9; t++) {
        CP_WAIT(0);
        __syncthreads();                 // fill(t) complete everywhere; mma(t-1) done everywhere
        if (t < KK9 - 1) fillA(t + 1, (t + 1) & 1);
        const uint32_t* cur = valS + (t & 1) * BUFW;
#pragma unroll
        for (int s2 = 0; s2 < 4; s2++) {
            int kb = s2 * 16 + lt * 4;
            uint4 q[2][2];
#pragma unroll
            for (int mt = 0; mt < 2; mt++) {
                q[mt][0] = *(const uint4*)&cur[(wm + mt * 16 + lg) * A_STRIDE + kb];
                q[mt][1] = *(const uint4*)&cur[(wm + mt * 16 + 8 + lg) * A_STRIDE + kb];
            }
            uint4 bv0 = ((const uint4*)&g_wofff[((t * 2 + cogA) * 8 + 2 * s2) * 128])[lane];
            uint4 bv1 = ((const uint4*)&g_wofff[((t * 2 + cogA) * 8 + 2 * s2 + 1) * 128])[lane];
            uint32_t b00[2] = {bv0.x, bv0.y}, b01[2] = {bv0.z, bv0.w};
            uint32_t b10[2] = {bv1.x, bv1.y}, b11[2] = {bv1.z, bv1.w};
#pragma unroll
            for (int mt = 0; mt < 2; mt++) {
                uint32_t a0[4] = {q[mt][0].x, q[mt][1].x, q[mt][0].y, q[mt][1].y};
                uint32_t a1[4] = {q[mt][0].z, q[mt][1].z, q[mt][0].w, q[mt][1].w};
                mma_tf32(accA[mt][0], a0, b00);
                mma_tf32(accA[mt][1], a0, b01);
                mma_tf32(accA[mt][0], a1, b10);
                mma_tf32(accA[mt][1], a1, b11);
            }
        }
    }
    __syncthreads();                     // all mma done before offmS overlays buf0

    // phase A epilogue -> offmS
#pragma unroll
    for (int mt = 0; mt < 2; mt++)
#pragma unroll
        for (int nt = 0; nt < 2; nt++)
#pragma unroll
            for (int r = 0; r < 4; r++) {
                int pix = wm + mt * 16 + ((r >> 1) << 3) + lg;
                int ch = cogA * 16 + nt * 8 + 2 * lt + (r & 1);
                if (ch < 27) {
                    float v = accA[mt][nt][r] + __ldg(&b_off[ch]);
                    if (ch >= 18) v = 1.f / (1.f + __expf(-v));
                    offmS[pix * 28 + ch] = v;
                }
            }
    __syncthreads();

    // ============ metadata: bilinear coefficients for all 9 taps ============
    for (int e = tid; e < KK9 * 128; e += 256) {
        int t = e / 128;
        int pl = e & 127;
        int rem = rem0 + pl;
        int y = rem / Ww;
        int x = rem % Ww;
        float dy = offmS[pl * 28 + 2 * t];
        float dx = offmS[pl * 28 + 2 * t + 1];
        float m = offmS[pl * 28 + 18 + t];
        int ky = t / 3, kx = t % 3;
        float py = (float)(y + ky - 1) + dy;
        float px = (float)(x + kx - 1) + dx;
        float fy = floorf(py), fx = floorf(px);
        float ly = py - fy, lx = px - fx;
        int iy = (int)fy, ix = (int)fx;
        float hy0 = (iy >= 0 && iy < Hh) ? (1.f - ly) : 0.f;
        float hy1 = (iy >= -1 && iy < Hh - 1) ? ly : 0.f;
        float hx0 = (ix >= 0 && ix < Ww) ? (1.f - lx) : 0.f;
        float hx1 = (ix >= -1 && ix < Ww - 1) ? lx : 0.f;
        int iyc = min(max(iy, 0), Hh - 1);
        int ixc = min(max(ix, 0), Ww - 1);
        int ddy = (iy >= 0 && iy < Hh - 1) ? Ww * Cc : 0;
        int ddx = (ix >= 0 && ix < Ww - 1) ? Cc : 0;
        entB[e] = ((nb * Hh + iyc) * Ww + ixc) * Cc;   // overwrites obase (dead)
        entD[e] = ddx | (ddy << 16);
        entW[e] = make_float4(hy0 * hx0 * m, hy0 * hx1 * m, hy1 * hx0 * m, hy1 * hx1 * m);
    }

    // ============ phase B: deform (128pix x 64co, warp tile 32pix x 32co) ============
    int cog = wid >> 2;           // co group (32 co each), 0..1
    int c4 = (tid & 15) << 2;     // gather channel position (float4 granule)
    int q4 = tid >> 4;            // gather pixel phase (0..15)

    float acc[2][4][4];
#pragma unroll
    for (int mt = 0; mt < 2; mt++)
#pragma unroll
        for (int nt = 0; nt < 4; nt++)
#pragma unroll
            for (int r = 0; r < 4; r++) acc[mt][nt][r] = 0.f;
    __syncthreads();              // metadata visible; offmS/valS free

    // vectorized gather of tap -> buffer (short live ranges; MLP across iterations)
    auto gatherB = [&](int tt, uint32_t* dst) {
        int tb = tt * 128;
#pragma unroll
        for (int s = 0; s < 8; s++) {
            int pl = s * 16 + q4;
            int e = tb + pl;
            float4 w = entW[e];
            int gbase = entB[e] + c4;
            int dd = entD[e];
            int ddx = dd & 0xffff;
            int ddy = dd >> 16;
            float4 v00 = *(const float4*)&xtf[gbase];
            float4 v01 = *(const float4*)&xtf[gbase + ddx];
            float4 v10 = *(const float4*)&xtf[gbase + ddy];
            float4 v11 = *(const float4*)&xtf[gbase + ddy + ddx];
            uint4 o;
            o.x = f2tf32(w.x * v00.x + w.y * v01.x + w.z * v10.x + w.w * v11.x);
            o.y = f2tf32(w.x * v00.y + w.y * v01.y + w.z * v10.y + w.w * v11.y);
            o.z = f2tf32(w.x * v00.z + w.y * v01.z + w.z * v10.z + w.w * v11.z);
            o.w = f2tf32(w.x * v00.w + w.y * v01.w + w.z * v10.w + w.w * v11.w);
            *(uint4*)&dst[pl * A_STRIDE + c4] = o;
        }
    };

    // prologue gather: tap 0 -> buf 0
    gatherB(0, valS);
    __syncthreads();

    for (int t = 0; t < KK9; t++) {
        const uint32_t* cur = valS + (t & 1) * BUFW;
#pragma unroll
        for (int s2 = 0; s2 < 4; s2++) {
            int kb = s2 * 16 + lt * 4;
            uint4 q[2][2];
#pragma unroll
            for (int mt = 0; mt < 2; mt++) {
                q[mt][0] = *(const uint4*)&cur[(wm + mt * 16 + lg) * A_STRIDE + kb];
                q[mt][1] = *(const uint4*)&cur[(wm + mt * 16 + 8 + lg) * A_STRIDE + kb];
            }
#pragma unroll
            for (int h = 0; h < 2; h++) {           // two 16-co halves of this warp's 32 co
                int oc = cog * 2 + h;               // old cog index in g_wtf
                uint4 bv0 = ((const uint4*)&g_wtf[((t * 4 + oc) * 8 + 2 * s2) * 128])[lane];
                uint4 bv1 = ((const uint4*)&g_wtf[((t * 4 + oc) * 8 + 2 * s2 + 1) * 128])[lane];
                uint32_t b00[2] = {bv0.x, bv0.y}, b01[2] = {bv0.z, bv0.w};
                uint32_t b10[2] = {bv1.x, bv1.y}, b11[2] = {bv1.z, bv1.w};
#pragma unroll
                for (int mt = 0; mt < 2; mt++) {
                    uint32_t a0[4] = {q[mt][0].x, q[mt][1].x, q[mt][0].y, q[mt][1].y};
                    uint32_t a1[4] = {q[mt][0].z, q[mt][1].z, q[mt][0].w, q[mt][1].w};
                    mma_tf32(acc[mt][2 * h + 0], a0, b00);
                    mma_tf32(acc[mt][2 * h + 1], a0, b01);
                    mma_tf32(acc[mt][2 * h + 0], a1, b10);
                    mma_tf32(acc[mt][2 * h + 1], a1, b11);
                }
            }
        }
        if (t < KK9 - 1) {
            gatherB(t + 1, valS + ((t + 1) & 1) * BUFW);
        }
        __syncthreads();
    }

    // epilogue: fragments -> smem [co][pix] -> coalesced NCHW stores
#pragma unroll
    for (int mt = 0; mt < 2; mt++)
#pragma unroll
        for (int nt = 0; nt < 4; nt++)
#pragma unroll
            for (int r = 0; r < 4; r++) {
                int pix = wm + mt * 16 + ((r >> 1) << 3) + lg;
                int co = cog * 32 + nt * 8 + 2 * lt + (r & 1);
                outS[co * O_STRIDE + pix] = acc[mt][nt][r];
            }
    __syncthreads();

#pragma unroll
    for (int i = 0; i < 8; i++) {
        int co = i * 8 + wid;
        int px = lane * 4;
        float4 v = *(const float4*)&outS[co * O_STRIDE + px];
        float bv = __ldg(&bias[co]);
        v.x += bv; v.y += bv; v.z += bv; v.w += bv;
        *(float4*)&out[((size_t)nb * COo + co) * HW + rem0 + px] = v;
    }
}

// ---------------- launch ----------------
extern "C" void kernel_launch(void* const* d_in, const int* in_sizes, int n_in,
                              void* d_out, int out_size) {
    const float* x      = (const float*)d_in[0];
    const float* w_off  = (const float*)d_in[1];
    const float* b_off  = (const float*)d_in[2];
    const float* weight = (const float*)d_in[3];
    const float* bias   = (const float*)d_in[4];
    float* out = (float*)d_out;

    static int attr_set = 0;
    if (!attr_set) {
        cudaFuncSetAttribute(k_fused, cudaFuncAttributeMaxDynamicSharedMemorySize, FUSED_SMEM);
        attr_set = 1;
    }

    k_prep<<<TP_BLOCKS + 216, 256>>>(x, weight, w_off);
    k_fused<<<NPIX / 128, 256, FUSED_SMEM>>>(b_off, bias, out);
}

// round 17
// speedup vs baseline: 1.7149x; 1.5006x over previous
#include <cuda_runtime.h>
#include <cuda_fp16.h>
#include <cstdint>

// Problem constants
#define Nn 8
#define Cc 64
#define Hh 96
#define Ww 96
#define COo 64
#define KK9 9
#define HW 9216           // 96*96
#define NPIX 73728        // 8*9216

// ---------------- scratch (device globals; no allocation allowed) ----------------
// x NHWC fp16, channels PERMUTED for m16n8k16 fragments:
//   c -> pos = (kk>>1)*32 + lt*8 + (kk&1)*4 + h8*2 + p
//   where kk=c>>4 (k-step), cc=c&15, h8=cc>>3, lt=(cc&7)>>1, p=c&1
__device__ __align__(16) __half g_xh[Nn * Hh * Ww * Cc];
// fp16 fragment-major weights, one uint4 per (lane, chunk):
// g_wtf4:  [t][cog2][k4][np2][lane32] -> {nt=2np: b0,b1, nt=2np+1: b0,b1}
// g_woff4: [t][cogA2][k4][lane32]     -> {nt0: b0,b1, nt1: b0,b1}
__device__ __align__(16) uint4 g_wtf4[KK9 * 2 * 4 * 2 * 32];    // 73728 B
__device__ __align__(16) uint4 g_woff4[KK9 * 2 * 4 * 32];       // 36864 B

static __device__ __forceinline__ uint32_t smem_u32(const void* p) {
    uint32_t a;
    asm("{ .reg .u64 t; cvta.to.shared.u64 t, %1; cvt.u32.u64 %0, t; }" : "=r"(a) : "l"(p));
    return a;
}
static __device__ __forceinline__ void mma_f16(float* d, const uint32_t* a, const uint32_t* b) {
    asm volatile("mma.sync.aligned.m16n8k16.row.col.f32.f16.f16.f32 "
                 "{%0,%1,%2,%3}, {%4,%5,%6,%7}, {%8,%9}, {%0,%1,%2,%3};"
                 : "+f"(d[0]), "+f"(d[1]), "+f"(d[2]), "+f"(d[3])
                 : "r"(a[0]), "r"(a[1]), "r"(a[2]), "r"(a[3]), "r"(b[0]), "r"(b[1]));
}
// fp32 bilinear combine of one half2 channel pair from 4 corners
static __device__ __forceinline__ uint32_t bil2(uint32_t c00, uint32_t c01, uint32_t c10,
                                                uint32_t c11, float4 w) {
    float2 f00 = __half22float2(*(__half2*)&c00);
    float2 f01 = __half22float2(*(__half2*)&c01);
    float2 f10 = __half22float2(*(__half2*)&c10);
    float2 f11 = __half22float2(*(__half2*)&c11);
    float r0 = w.x * f00.x + w.y * f01.x + w.z * f10.x + w.w * f11.x;
    float r1 = w.x * f00.y + w.y * f01.y + w.z * f10.y + w.w * f11.y;
    __half2 h = __floats2half2_rn(r0, r1);
    return *(uint32_t*)&h;
}
#define CP_ASYNC16(dst, src, sz) \
    asm volatile("cp.async.cg.shared.global [%0], [%1], 16, %2;" :: "r"(dst), "l"(src), "r"(sz) : "memory")
#define CP_COMMIT() asm volatile("cp.async.commit_group;" ::: "memory")
#define CP_WAIT(n)  asm volatile("cp.async.wait_group %0;" :: "n"(n) : "memory")

// ---------------- kernel 0: x transpose -> fp16 permuted NHWC + weight prep ----------------
#define TP_BLOCKS 2304        // 3 wtiles * 768 (n*y)
__global__ void k_prep(const float* __restrict__ x,
                       const float* __restrict__ weight,
                       const float* __restrict__ w_off) {
    int b = blockIdx.x;
    int tid = threadIdx.x;
    if (b < TP_BLOCKS) {
        __shared__ float tile[2][32][33];
        int xb = (b % 3) * 32;
        int z = b / 3;
        int n = z / Hh;
        int y = z % Hh;
        int tx = tid & 31, ty = tid >> 5;
#pragma unroll
        for (int cb2 = 0; cb2 < 2; cb2++)
#pragma unroll
            for (int k = 0; k < 4; k++) {
                int c = cb2 * 32 + ty + k * 8;
                tile[cb2][ty + k * 8][tx] = x[((n * Cc + c) * Hh + y) * Ww + xb + tx];
            }
        __syncthreads();
        // each thread writes channel pair (2*tx, 2*tx+1) as half2
        int c0 = 2 * tx;
        int kk = c0 >> 4, cc = c0 & 15, h8 = cc >> 3, lt = (cc & 7) >> 1;
        int posb = (kk >> 1) * 32 + lt * 8 + (kk & 1) * 4 + h8 * 2;   // even
        int cb = c0 >> 5, ci = c0 & 31;
#pragma unroll
        for (int k = 0; k < 4; k++) {
            int xi = ty + k * 8;
            __half2 hv = __floats2half2_rn(tile[cb][ci][xi], tile[cb][ci + 1][xi]);
            *(__half2*)&g_xh[((n * Hh + y) * Ww + xb + xi) * Cc + posb] = hv;
        }
    } else {
        int gidx = (b - TP_BLOCKS) * 256 + tid;     // over 36864 + 18432 halves
        if (gidx < KK9 * 4096) {
            int i = gidx;
            int hw = i & 7, lane = (i >> 3) & 31, np = (i >> 8) & 1;
            int k = (i >> 9) & 3, cog = (i >> 11) & 1, t = i >> 12;
            int nt = np * 2 + (hw >> 2), bsel = (hw >> 1) & 1, p = hw & 1;
            int co = cog * 32 + nt * 8 + (lane >> 2);
            int c = 16 * k + 2 * (lane & 3) + bsel * 8 + p;
            ((__half*)g_wtf4)[i] = __float2half(weight[(co * Cc + c) * KK9 + t]);
        } else if (gidx < KK9 * 4096 + KK9 * 2048) {
            int i = gidx - KK9 * 4096;
            int hw = i & 7, lane = (i >> 3) & 31;
            int k = (i >> 8) & 3, cog = (i >> 10) & 1, t = i >> 11;
            int nt = hw >> 2, bsel = (hw >> 1) & 1, p = hw & 1;
            int ch = cog * 16 + nt * 8 + (lane >> 2);
            int c = 16 * k + 2 * (lane & 3) + bsel * 8 + p;
            ((__half*)g_woff4)[i] = (ch < 27) ? __float2half(w_off[(ch * Cc + c) * KK9 + t])
                                              : __float2half(0.f);
        }
    }
}

// ---------------- fused kernel: offconv (TC fp16) -> metadata -> deform (TC fp16) ----------
// 256 threads / 8 warps; 128-pixel tile; warp tiles 32x16 (A) / 32x32 (B).
#define ASTR 96                                // halves per valS row (192 B: conflict-free)
#define O_STRIDE 132
#define BUFH (128 * ASTR)                      // 12288 halves per buffer (24576 B)
#define SM_ENTW (2 * BUFH * 2)                 // 49152
#define SM_ENTBD (SM_ENTW + 1152 * 16)         // 67584  (obase overlays here)
#define FUSED_SMEM (SM_ENTBD + 1152 * 8)       // 76800

__global__ void __launch_bounds__(256, 2) k_fused(const float* __restrict__ b_off,
                                                  const float* __restrict__ bias,
                                                  float* __restrict__ out) {
    extern __shared__ char base[];
    __half*  valS = (__half*)base;                   // [2][128][96]
    float4*  entW = (float4*)(base + SM_ENTW);
    int2*    entBD = (int2*)(base + SM_ENTBD);
    int*     obase = (int*)(base + SM_ENTBD);        // overlay (dead before entBD written)
    float*   offmS = (float*)base;                   // [128][28] overlay
    float*   outS = (float*)base;                    // epilogue overlay [64co][132]
    uint32_t valS_sm = smem_u32(valS);

    int tid = threadIdx.x;
    int wid = tid >> 5;           // 0..7
    int lane = tid & 31;
    int pix0 = blockIdx.x * 128;
    int nb = pix0 / HW;
    int rem0 = pix0 % HW;
    int lg = lane >> 2;
    int lt = lane & 3;

    // ============ phase A: offset conv (warp tile 32pix x 16ch) ============
    for (int e = tid; e < KK9 * 128; e += 256) {
        int t = e / 128;
        int pl = e & 127;
        int rem = rem0 + pl;
        int yy = rem / Ww + t / 3 - 1;
        int xx = rem % Ww + t % 3 - 1;
        obase[e] = ((unsigned)yy < Hh && (unsigned)xx < Ww)
                 ? ((nb * Hh + yy) * Ww + xx) * Cc : -1;
    }
    __syncthreads();

    int wm = (wid & 3) * 32;      // warp pixel base (both phases)
    int cogA = wid >> 2;          // ch group (16 ch)
    int g8 = tid & 7;             // 16B channel granule (gather/fill)

    float accA[2][2][4];
#pragma unroll
    for (int mt = 0; mt < 2; mt++)
#pragma unroll
        for (int nt = 0; nt < 2; nt++)
#pragma unroll
            for (int r = 0; r < 4; r++) accA[mt][nt][r] = 0.f;

    auto fillA = [&](int tt, int bsel) {
        uint32_t dbase = valS_sm + bsel * (BUFH * 2);
#pragma unroll
        for (int j = 0; j < 4; j++) {
            int idx = tid + j * 256;
            int pl = idx >> 3;
            int gg = idx & 7;
            int gb = obase[tt * 128 + pl];
            const __half* src = &g_xh[(gb < 0 ? 0 : gb) + gg * 8];
            CP_ASYNC16(dbase + pl * 192 + gg * 16, src, (gb < 0) ? 0 : 16);
        }
        CP_COMMIT();
    };

    fillA(0, 0);
    for (int t = 0; t < KK9; t++) {
        CP_WAIT(0);
        __syncthreads();
        if (t < KK9 - 1) fillA(t + 1, (t + 1) & 1);
        const __half* cur = valS + (t & 1) * BUFH;
#pragma unroll
        for (int s = 0; s < 2; s++) {
            uint4 q[2][2];
#pragma unroll
            for (int mt = 0; mt < 2; mt++) {
                q[mt][0] = *(const uint4*)&cur[(wm + mt * 16 + lg) * ASTR + s * 32 + lt * 8];
                q[mt][1] = *(const uint4*)&cur[(wm + mt * 16 + 8 + lg) * ASTR + s * 32 + lt * 8];
            }
#pragma unroll
            for (int k2 = 0; k2 < 2; k2++) {
                int k = 2 * s + k2;
                uint4 bv = g_woff4[((t * 2 + cogA) * 4 + k) * 32 + lane];
                uint32_t b0[2] = {bv.x, bv.y}, b1[2] = {bv.z, bv.w};
#pragma unroll
                for (int mt = 0; mt < 2; mt++) {
                    uint32_t a[4];
                    if (k2 == 0) { a[0] = q[mt][0].x; a[1] = q[mt][1].x; a[2] = q[mt][0].y; a[3] = q[mt][1].y; }
                    else         { a[0] = q[mt][0].z; a[1] = q[mt][1].z; a[2] = q[mt][0].w; a[3] = q[mt][1].w; }
                    mma_f16(accA[mt][0], a, b0);
                    mma_f16(accA[mt][1], a, b1);
                }
            }
        }
    }
    __syncthreads();                     // all mma done before offmS overlays buf0

    // phase A epilogue -> offmS
#pragma unroll
    for (int mt = 0; mt < 2; mt++)
#pragma unroll
        for (int nt = 0; nt < 2; nt++)
#pragma unroll
            for (int r = 0; r < 4; r++) {
                int pix = wm + mt * 16 + ((r >> 1) << 3) + lg;
                int ch = cogA * 16 + nt * 8 + 2 * lt + (r & 1);
                if (ch < 27) {
                    float v = accA[mt][nt][r] + __ldg(&b_off[ch]);
                    if (ch >= 18) v = 1.f / (1.f + __expf(-v));
                    offmS[pix * 28 + ch] = v;
                }
            }
    __syncthreads();

    // ============ metadata: bilinear coefficients for all 9 taps ============
    for (int e = tid; e < KK9 * 128; e += 256) {
        int t = e / 128;
        int pl = e & 127;
        int rem = rem0 + pl;
        int y = rem / Ww;
        int x = rem % Ww;
        float dy = offmS[pl * 28 + 2 * t];
        float dx = offmS[pl * 28 + 2 * t + 1];
        float m = offmS[pl * 28 + 18 + t];
        int ky = t / 3, kx = t % 3;
        float py = (float)(y + ky - 1) + dy;
        float px = (float)(x + kx - 1) + dx;
        float fy = floorf(py), fx = floorf(px);
        float ly = py - fy, lx = px - fx;
        int iy = (int)fy, ix = (int)fx;
        float hy0 = (iy >= 0 && iy < Hh) ? (1.f - ly) : 0.f;
        float hy1 = (iy >= -1 && iy < Hh - 1) ? ly : 0.f;
        float hx0 = (ix >= 0 && ix < Ww) ? (1.f - lx) : 0.f;
        float hx1 = (ix >= -1 && ix < Ww - 1) ? lx : 0.f;
        int iyc = min(max(iy, 0), Hh - 1);
        int ixc = min(max(ix, 0), Ww - 1);
        int ddy = (iy >= 0 && iy < Hh - 1) ? Ww * Cc : 0;
        int ddx = (ix >= 0 && ix < Ww - 1) ? Cc : 0;
        entW[e] = make_float4(hy0 * hx0 * m, hy0 * hx1 * m, hy1 * hx0 * m, hy1 * hx1 * m);
        entBD[e] = make_int2(((nb * Hh + iyc) * Ww + ixc) * Cc, ddx | (ddy << 16));
    }

    // ============ phase B: deform (warp tile 32pix x 32co) ============
    int cog = wid >> 2;           // co group (32 co)

    float acc[2][4][4];
#pragma unroll
    for (int mt = 0; mt < 2; mt++)
#pragma unroll
        for (int nt = 0; nt < 4; nt++)
#pragma unroll
            for (int r = 0; r < 4; r++) acc[mt][nt][r] = 0.f;
    __syncthreads();              // metadata visible; offmS/valS free

    auto gatherB = [&](int tt, __half* dst) {
        int tb = tt * 128;
#pragma unroll
        for (int s4 = 0; s4 < 4; s4++) {
            int pl = s4 * 32 + (tid >> 3);
            int e = tb + pl;
            float4 w = entW[e];
            int2 bd = entBD[e];
            int gbase = bd.x + g8 * 8;
            int ddx = bd.y & 0xffff;
            int ddy = bd.y >> 16;
            uint4 u00 = *(const uint4*)&g_xh[gbase];
            uint4 u01 = *(const uint4*)&g_xh[gbase + ddx];
            uint4 u10 = *(const uint4*)&g_xh[gbase + ddy];
            uint4 u11 = *(const uint4*)&g_xh[gbase + ddy + ddx];
            uint4 o;
            o.x = bil2(u00.x, u01.x, u10.x, u11.x, w);
            o.y = bil2(u00.y, u01.y, u10.y, u11.y, w);
            o.z = bil2(u00.z, u01.z, u10.z, u11.z, w);
            o.w = bil2(u00.w, u01.w, u10.w, u11.w, w);
            *(uint4*)&dst[pl * ASTR + g8 * 8] = o;
        }
    };

    gatherB(0, valS);
    __syncthreads();

    for (int t = 0; t < KK9; t++) {
        const __half* cur = valS + (t & 1) * BUFH;
#pragma unroll
        for (int s = 0; s < 2; s++) {
            uint4 q[2][2];
#pragma unroll
            for (int mt = 0; mt < 2; mt++) {
                q[mt][0] = *(const uint4*)&cur[(wm + mt * 16 + lg) * ASTR + s * 32 + lt * 8];
                q[mt][1] = *(const uint4*)&cur[(wm + mt * 16 + 8 + lg) * ASTR + s * 32 + lt * 8];
            }
#pragma unroll
            for (int k2 = 0; k2 < 2; k2++) {
                int k = 2 * s + k2;
#pragma unroll
                for (int np = 0; np < 2; np++) {
                    uint4 bv = g_wtf4[(((t * 2 + cog) * 4 + k) * 2 + np) * 32 + lane];
                    uint32_t b0[2] = {bv.x, bv.y}, b1[2] = {bv.z, bv.w};
#pragma unroll
                    for (int mt = 0; mt < 2; mt++) {
                        uint32_t a[4];
                        if (k2 == 0) { a[0] = q[mt][0].x; a[1] = q[mt][1].x; a[2] = q[mt][0].y; a[3] = q[mt][1].y; }
                        else         { a[0] = q[mt][0].z; a[1] = q[mt][1].z; a[2] = q[mt][0].w; a[3] = q[mt][1].w; }
                        mma_f16(acc[mt][np * 2 + 0], a, b0);
                        mma_f16(acc[mt][np * 2 + 1], a, b1);
                    }
                }
            }
        }
        if (t < KK9 - 1) {
            gatherB(t + 1, valS + ((t + 1) & 1) * BUFH);
        }
        __syncthreads();
    }

    // epilogue: fragments -> smem [co][pix] -> coalesced NCHW stores
#pragma unroll
    for (int mt = 0; mt < 2; mt++)
#pragma unroll
        for (int nt = 0; nt < 4; nt++)
#pragma unroll
            for (int r = 0; r < 4; r++) {
                int pix = wm + mt * 16 + ((r >> 1) << 3) + lg;
                int co = cog * 32 + nt * 8 + 2 * lt + (r & 1);
                outS[co * O_STRIDE + pix] = acc[mt][nt][r];
            }
    __syncthreads();

#pragma unroll
    for (int i = 0; i < 8; i++) {
        int co = i * 8 + wid;
        int px = lane * 4;
        float4 v = *(const float4*)&outS[co * O_STRIDE + px];
        float bv = __ldg(&bias[co]);
        v.x += bv; v.y += bv; v.z += bv; v.w += bv;
        *(float4*)&out[((size_t)nb * COo + co) * HW + rem0 + px] = v;
    }
}

// ---------------- launch ----------------
extern "C" void kernel_launch(void* const* d_in, const int* in_sizes, int n_in,
                              void* d_out, int out_size) {
    const float* x      = (const float*)d_in[0];
    const float* w_off  = (const float*)d_in[1];
    const float* b_off  = (const float*)d_in[2];
    const float* weight = (const float*)d_in[3];
    const float* bias   = (const float*)d_in[4];
    float* out = (float*)d_out;

    static int attr_set = 0;
    if (!attr_set) {
        cudaFuncSetAttribute(k_fused, cudaFuncAttributeMaxDynamicSharedMemorySize, FUSED_SMEM);
        attr_set = 1;
    }

    k_prep<<<TP_BLOCKS + 216, 256>>>(x, weight, w_off);
    k_fused<<<NPIX / 128, 256, FUSED_SMEM>>>(b_off, bias, out);
}